// round 6
// baseline (speedup 1.0000x reference)
#include <cuda_runtime.h>
#include <math.h>

#define DIM    1024
#define NHEADS 16
#define DHEAD  64
#define NTOK   2048
#define NB     2
#define NROWS  (NB * NTOK)   // 4096

// ---------------- scratch (no allocations allowed) ----------------
__device__ float g_xn[NROWS * DIM];
__device__ float g_q[NROWS * DIM];
__device__ float g_k[NROWS * DIM];
__device__ float g_v[NROWS * DIM];
__device__ float g_att[NROWS * DIM];
__device__ float g_invfreq[32];

// ---------------- inv_freq table (hoists fp64 pow out of hot path) ----------
__global__ void init_invfreq_kernel()
{
    int i = threadIdx.x;   // 0..31
    g_invfreq[i] = (float)(1.0 / pow(10000.0, (double)(2 * i) / 64.0));
}

// ---------------- RMSNorm ----------------
__global__ __launch_bounds__(256)
void rmsnorm_kernel(const float* __restrict__ x, const float* __restrict__ w,
                    float* __restrict__ out)
{
    int row = blockIdx.x;
    const float* xr = x + (size_t)row * DIM;
    float* outr = out + (size_t)row * DIM;
    int tid = threadIdx.x;

    float4 v = ((const float4*)xr)[tid];             // 256 threads * 4 = 1024
    float ss = v.x * v.x + v.y * v.y + v.z * v.z + v.w * v.w;
    #pragma unroll
    for (int o = 16; o > 0; o >>= 1) ss += __shfl_xor_sync(0xffffffffu, ss, o);

    __shared__ float warpsum[8];
    __shared__ float rstd_s;
    if ((tid & 31) == 0) warpsum[tid >> 5] = ss;
    __syncthreads();
    if (tid == 0) {
        float t = 0.f;
        #pragma unroll
        for (int i = 0; i < 8; i++) t += warpsum[i];
        rstd_s = rsqrtf(t * (1.0f / DIM) + 1.1920929e-07f);
    }
    __syncthreads();
    float rstd = rstd_s;

    float4 wv = ((const float4*)w)[tid];
    float4 o4;
    o4.x = v.x * rstd * wv.x;
    o4.y = v.y * rstd * wv.y;
    o4.z = v.z * rstd * wv.z;
    o4.w = v.w * rstd * wv.w;
    ((float4*)outr)[tid] = o4;
}

// ---------------- NT GEMM: C[M,N] = A[M,K] * B[N,K]^T ----------------
// M=4096, N=K=1024 fixed. 128x128 tile, BK=8, 256 threads, 8x8 microtile,
// double-buffered smem (one barrier per k-step), global prefetch overlapped.
// gridDim.z selects among up to 3 (B, C) pairs so QKV runs as ONE launch.
#define GK 1024
#define GN 1024

__global__ __launch_bounds__(256)
void gemm_nt_kernel(const float* __restrict__ A,
                    const float* __restrict__ B0, const float* __restrict__ B1,
                    const float* __restrict__ B2,
                    float* __restrict__ C0, float* __restrict__ C1,
                    float* __restrict__ C2)
{
    __shared__ float As[2][8][128];
    __shared__ float Bs[2][8][128];

    int z = blockIdx.z;
    const float* B = (z == 0) ? B0 : ((z == 1) ? B1 : B2);
    float* C = (z == 0) ? C0 : ((z == 1) ? C1 : C2);

    int tid = threadIdx.x;
    int tx = tid & 15;    // N direction
    int ty = tid >> 4;    // M direction
    int bm = blockIdx.y * 128;
    int bn = blockIdx.x * 128;

    int lrow = tid >> 1;          // 0..127
    int lcol = (tid & 1) * 4;     // 0 or 4
    const float* Ag = A + (size_t)(bm + lrow) * GK + lcol;
    const float* Bg = B + (size_t)(bn + lrow) * GK + lcol;

    float acc[8][8];
    #pragma unroll
    for (int i = 0; i < 8; i++)
        #pragma unroll
        for (int j = 0; j < 8; j++) acc[i][j] = 0.f;

    // prologue: tile 0 -> buf 0
    {
        float4 a4 = *(const float4*)(Ag);
        float4 b4 = *(const float4*)(Bg);
        As[0][lcol + 0][lrow] = a4.x; As[0][lcol + 1][lrow] = a4.y;
        As[0][lcol + 2][lrow] = a4.z; As[0][lcol + 3][lrow] = a4.w;
        Bs[0][lcol + 0][lrow] = b4.x; Bs[0][lcol + 1][lrow] = b4.y;
        Bs[0][lcol + 2][lrow] = b4.z; Bs[0][lcol + 3][lrow] = b4.w;
    }
    __syncthreads();

    int buf = 0;
    for (int k0 = 0; k0 < GK; k0 += 8) {
        bool has_next = (k0 + 8 < GK);
        float4 na, nb;
        if (has_next) {
            na = *(const float4*)(Ag + k0 + 8);
            nb = *(const float4*)(Bg + k0 + 8);
        }

        #pragma unroll
        for (int kk = 0; kk < 8; kk++) {
            float4 a0 = ((const float4*)As[buf][kk])[ty];
            float4 a1 = ((const float4*)As[buf][kk])[ty + 16];
            float4 b0 = ((const float4*)Bs[buf][kk])[tx];
            float4 b1 = ((const float4*)Bs[buf][kk])[tx + 16];
            float ra[8] = {a0.x, a0.y, a0.z, a0.w, a1.x, a1.y, a1.z, a1.w};
            float rb[8] = {b0.x, b0.y, b0.z, b0.w, b1.x, b1.y, b1.z, b1.w};
            #pragma unroll
            for (int i = 0; i < 8; i++)
                #pragma unroll
                for (int j = 0; j < 8; j++)
                    acc[i][j] += ra[i] * rb[j];
        }

        if (has_next) {
            int nbuf = buf ^ 1;
            As[nbuf][lcol + 0][lrow] = na.x; As[nbuf][lcol + 1][lrow] = na.y;
            As[nbuf][lcol + 2][lrow] = na.z; As[nbuf][lcol + 3][lrow] = na.w;
            Bs[nbuf][lcol + 0][lrow] = nb.x; Bs[nbuf][lcol + 1][lrow] = nb.y;
            Bs[nbuf][lcol + 2][lrow] = nb.z; Bs[nbuf][lcol + 3][lrow] = nb.w;
            __syncthreads();
            buf = nbuf;
        }
    }

    #pragma unroll
    for (int i = 0; i < 8; i++) {
        int ri = bm + ((i < 4) ? (ty * 4 + i) : (64 + ty * 4 + i - 4));
        float4 c0 = make_float4(acc[i][0], acc[i][1], acc[i][2], acc[i][3]);
        float4 c1 = make_float4(acc[i][4], acc[i][5], acc[i][6], acc[i][7]);
        *(float4*)(C + (size_t)ri * GN + bn + tx * 4) = c0;
        *(float4*)(C + (size_t)ri * GN + bn + 64 + tx * 4) = c1;
    }
}

// ---------------- RoPE (in-place, optional pre-scale) ----------------
__global__ __launch_bounds__(256)
void rope_kernel(float* __restrict__ x, float scale)
{
    int p = blockIdx.x * blockDim.x + threadIdx.x;   // pair index
    int pd  = p & 511;         // pair within row (0..511)
    int row = p >> 9;
    int tok = row & (NTOK - 1);
    int i   = pd & 31;         // pair within head (0..31)

    float inv = g_invfreq[i];
    float ang = (float)tok * inv;
    float s, c;
    sincosf(ang, &s, &c);

    float* px = x + (size_t)row * DIM + 2 * pd;
    float x0 = px[0] * scale, x1 = px[1] * scale;
    px[0] = x0 * c - x1 * s;
    px[1] = x1 * c + x0 * s;
}

// ---------------- Causal flash attention (fp32) ----------------
// grid: (NTOK/128, NB*NHEADS). 128 threads, 1 thread = 1 query row.
// q/k/v/o all stored [b, tok, head*64+d] (row stride DIM).
__global__ __launch_bounds__(128)
void attn_kernel(const float* __restrict__ q, const float* __restrict__ k,
                 const float* __restrict__ v, float* __restrict__ o)
{
    extern __shared__ float sm[];
    float* Ks = sm;                  // 64*64
    float* Vs = sm + 64 * 64;        // 64*64
    float* S  = sm + 2 * 64 * 64;    // 128*65 (padded, conflict-free)

    int bh = blockIdx.y;
    int b = bh >> 4, h = bh & 15;
    const size_t base = (size_t)b * NTOK * DIM + (size_t)h * DHEAD;
    int tid = threadIdx.x;
    int qrow = blockIdx.x * 128 + tid;

    float qreg[64];
    #pragma unroll
    for (int t = 0; t < 16; t++) {
        float4 q4 = *(const float4*)(q + base + (size_t)qrow * DIM + t * 4);
        qreg[t * 4 + 0] = q4.x; qreg[t * 4 + 1] = q4.y;
        qreg[t * 4 + 2] = q4.z; qreg[t * 4 + 3] = q4.w;
    }

    float m = -1e30f, l = 0.f;
    float oa[64];
    #pragma unroll
    for (int t = 0; t < 64; t++) oa[t] = 0.f;

    int kend = blockIdx.x * 128 + 128;   // causal tile limit
    int lr = tid >> 1;
    int lc = (tid & 1) * 32;

    for (int j0 = 0; j0 < kend; j0 += 64) {
        __syncthreads();
        #pragma unroll
        for (int t = 0; t < 8; t++) {
            *(float4*)&Ks[lr * 64 + lc + t * 4] =
                *(const float4*)(k + base + (size_t)(j0 + lr) * DIM + lc + t * 4);
            *(float4*)&Vs[lr * 64 + lc + t * 4] =
                *(const float4*)(v + base + (size_t)(j0 + lr) * DIM + lc + t * 4);
        }
        __syncthreads();

        // jmax: number of unmasked keys in this tile for this query row
        int jmax = qrow - j0 + 1;             // may exceed 64 (fully unmasked)
        if (jmax > 64) jmax = 64;

        float mt = -1e30f;
        for (int j = 0; j < 64; j++) {
            const float4* kr = (const float4*)&Ks[j * 64];
            float s = 0.f;
            #pragma unroll
            for (int t = 0; t < 16; t++) {
                float4 k4 = kr[t];
                s += qreg[t * 4 + 0] * k4.x + qreg[t * 4 + 1] * k4.y
                   + qreg[t * 4 + 2] * k4.z + qreg[t * 4 + 3] * k4.w;
            }
            s = (j < jmax) ? s : -1e30f;
            S[tid * 65 + j] = s;
            mt = fmaxf(mt, s);
        }

        float mnew = fmaxf(m, mt);
        float alpha = __expf(m - mnew);
        l *= alpha;
        #pragma unroll
        for (int t = 0; t < 64; t++) oa[t] *= alpha;
        m = mnew;

        for (int j = 0; j < 64; j++) {
            float p = __expf(S[tid * 65 + j] - mnew);
            l += p;
            const float4* vr = (const float4*)&Vs[j * 64];
            #pragma unroll
            for (int t = 0; t < 16; t++) {
                float4 v4 = vr[t];
                oa[t * 4 + 0] += p * v4.x; oa[t * 4 + 1] += p * v4.y;
                oa[t * 4 + 2] += p * v4.z; oa[t * 4 + 3] += p * v4.w;
            }
        }
    }

    float inv = 1.f / l;
    #pragma unroll
    for (int t = 0; t < 16; t++) {
        float4 o4 = make_float4(oa[t * 4 + 0] * inv, oa[t * 4 + 1] * inv,
                                oa[t * 4 + 2] * inv, oa[t * 4 + 3] * inv);
        *(float4*)(o + base + (size_t)qrow * DIM + t * 4) = o4;
    }
}

// ---------------- launch ----------------
extern "C" void kernel_launch(void* const* d_in, const int* in_sizes, int n_in,
                              void* d_out, int out_size)
{
    const float* tokens = (const float*)d_in[0];
    const float* nw     = (const float*)d_in[1];
    const float* wq     = (const float*)d_in[2];
    const float* wk     = (const float*)d_in[3];
    const float* wv     = (const float*)d_in[4];
    const float* wo     = (const float*)d_in[5];
    float* out = (float*)d_out;

    float *xn, *qb, *kb, *vb, *ab;
    cudaGetSymbolAddress((void**)&xn, g_xn);
    cudaGetSymbolAddress((void**)&qb, g_q);
    cudaGetSymbolAddress((void**)&kb, g_k);
    cudaGetSymbolAddress((void**)&vb, g_v);
    cudaGetSymbolAddress((void**)&ab, g_att);

    init_invfreq_kernel<<<1, 32>>>();
    rmsnorm_kernel<<<NROWS, 256>>>(tokens, nw, xn);

    // QKV: one fused launch, 768 blocks
    gemm_nt_kernel<<<dim3(DIM / 128, NROWS / 128, 3), 256>>>(
        xn, wq, wk, wv, qb, kb, vb);

    int pairs = NROWS * DIM / 2;
    rope_kernel<<<pairs / 256, 256>>>(qb, 0.125f);   // 64^-0.5 folded in
    rope_kernel<<<pairs / 256, 256>>>(kb, 1.0f);

    const int ATTN_SMEM = (2 * 64 * 64 + 128 * 65) * (int)sizeof(float);
    cudaFuncSetAttribute(attn_kernel, cudaFuncAttributeMaxDynamicSharedMemorySize, ATTN_SMEM);
    attn_kernel<<<dim3(NTOK / 128, NB * NHEADS), 128, ATTN_SMEM>>>(qb, kb, vb, ab);

    // Output projection
    gemm_nt_kernel<<<dim3(DIM / 128, NROWS / 128, 1), 256>>>(
        ab, wo, wo, wo, out, out, out);
}

// round 9
// speedup vs baseline: 1.1934x; 1.1934x over previous
#include <cuda_runtime.h>
#include <cuda_bf16.h>
#include <math.h>
#include <stdint.h>

#define DIM    1024
#define NHEADS 16
#define DHEAD  64
#define NTOK   2048
#define NB     2
#define NROWS  (NB * NTOK)   // 4096
#define KC     3072          // tripled K for hi/lo split GEMM
#define WSZ    (1024 * KC)
#define GN     1024

// ---------------- scratch (no allocations allowed) ----------------
__device__ float g_q[NROWS * DIM];
__device__ float g_k[NROWS * DIM];
__device__ float g_v[NROWS * DIM];
__device__ __nv_bfloat16 g_xc[NROWS * KC];   // x normalized, split [hi|hi|lo]
__device__ __nv_bfloat16 g_ac[NROWS * KC];   // attn out, split [hi|hi|lo]
__device__ __nv_bfloat16 g_wc[4 * WSZ];      // wq,wk,wv,wo split [hi|lo|hi]
__device__ float g_invfreq[32];

// ================= PTX helpers (non-'a' features only) =================
__device__ __forceinline__ uint32_t smem_to_u32(const void* p) {
    uint32_t a;
    asm("{ .reg .u64 t; cvta.to.shared.u64 t, %1; cvt.u32.u64 %0, t; }" : "=r"(a) : "l"(p));
    return a;
}
__device__ __forceinline__ void ldsm_x4(uint32_t* r, uint32_t addr) {
    asm volatile("ldmatrix.sync.aligned.m8n8.x4.shared.b16 {%0,%1,%2,%3}, [%4];"
        : "=r"(r[0]), "=r"(r[1]), "=r"(r[2]), "=r"(r[3]) : "r"(addr));
}
__device__ __forceinline__ void ldsm_x2(uint32_t* r, uint32_t addr) {
    asm volatile("ldmatrix.sync.aligned.m8n8.x2.shared.b16 {%0,%1}, [%2];"
        : "=r"(r[0]), "=r"(r[1]) : "r"(addr));
}
__device__ __forceinline__ void mma16816(float* d, const uint32_t* a, const uint32_t* b) {
    asm volatile(
        "mma.sync.aligned.m16n8k16.row.col.f32.bf16.bf16.f32 "
        "{%0,%1,%2,%3}, {%4,%5,%6,%7}, {%8,%9}, {%0,%1,%2,%3};"
        : "+f"(d[0]), "+f"(d[1]), "+f"(d[2]), "+f"(d[3])
        : "r"(a[0]), "r"(a[1]), "r"(a[2]), "r"(a[3]), "r"(b[0]), "r"(b[1]));
}

// ---------------- hi/lo split store helper ----------------
__device__ __forceinline__ void split_store4(__nv_bfloat16* p_hi1, __nv_bfloat16* p_hi2,
                                             __nv_bfloat16* p_lo, float4 v)
{
    __nv_bfloat16 h0 = __float2bfloat16(v.x), h1 = __float2bfloat16(v.y);
    __nv_bfloat16 h2 = __float2bfloat16(v.z), h3 = __float2bfloat16(v.w);
    __nv_bfloat16 l0 = __float2bfloat16(v.x - __bfloat162float(h0));
    __nv_bfloat16 l1 = __float2bfloat16(v.y - __bfloat162float(h1));
    __nv_bfloat16 l2 = __float2bfloat16(v.z - __bfloat162float(h2));
    __nv_bfloat16 l3 = __float2bfloat16(v.w - __bfloat162float(h3));
    __nv_bfloat162 ha = __halves2bfloat162(h0, h1), hb = __halves2bfloat162(h2, h3);
    __nv_bfloat162 la = __halves2bfloat162(l0, l1), lb = __halves2bfloat162(l2, l3);
    *(__nv_bfloat162*)(p_hi1) = ha; *(__nv_bfloat162*)(p_hi1 + 2) = hb;
    *(__nv_bfloat162*)(p_hi2) = ha; *(__nv_bfloat162*)(p_hi2 + 2) = hb;
    *(__nv_bfloat162*)(p_lo)  = la; *(__nv_bfloat162*)(p_lo + 2)  = lb;
}

// ---------------- inv_freq table ----------------
__global__ void init_invfreq_kernel()
{
    int i = threadIdx.x;
    g_invfreq[i] = (float)(1.0 / pow(10000.0, (double)(2 * i) / 64.0));
}

// ---------------- RMSNorm fused with split-conversion ----------------
__global__ __launch_bounds__(256)
void rmsnorm_split_kernel(const float* __restrict__ x, const float* __restrict__ w)
{
    int row = blockIdx.x;
    const float* xr = x + (size_t)row * DIM;
    int tid = threadIdx.x;

    float4 v = ((const float4*)xr)[tid];
    float ss = v.x * v.x + v.y * v.y + v.z * v.z + v.w * v.w;
    #pragma unroll
    for (int o = 16; o > 0; o >>= 1) ss += __shfl_xor_sync(0xffffffffu, ss, o);

    __shared__ float warpsum[8];
    __shared__ float rstd_s;
    if ((tid & 31) == 0) warpsum[tid >> 5] = ss;
    __syncthreads();
    if (tid == 0) {
        float t = 0.f;
        #pragma unroll
        for (int i = 0; i < 8; i++) t += warpsum[i];
        rstd_s = rsqrtf(t * (1.0f / DIM) + 1.1920929e-07f);
    }
    __syncthreads();
    float rstd = rstd_s;

    float4 wv = ((const float4*)w)[tid];
    float4 o4 = make_float4(v.x * rstd * wv.x, v.y * rstd * wv.y,
                            v.z * rstd * wv.z, v.w * rstd * wv.w);
    __nv_bfloat16* base = g_xc + (size_t)row * KC;
    int col = tid * 4;
    split_store4(base + col, base + 1024 + col, base + 2048 + col, o4);  // [hi|hi|lo]
}

// ---------------- weight split-conversion: [hi | lo | hi] ----------------
__global__ __launch_bounds__(256)
void convert_w_kernel(const float* __restrict__ w0, const float* __restrict__ w1,
                      const float* __restrict__ w2, const float* __restrict__ w3)
{
    int z = blockIdx.z;
    const float* w = (z == 0) ? w0 : (z == 1) ? w1 : (z == 2) ? w2 : w3;
    int p = blockIdx.x * 256 + threadIdx.x;
    int row = p >> 8;
    int c4 = (p & 255) * 4;
    float4 v = *(const float4*)(w + (size_t)row * 1024 + c4);
    __nv_bfloat16* base = g_wc + (size_t)z * WSZ + (size_t)row * KC;
    split_store4(base + c4, base + 2048 + c4, base + 1024 + c4, v);      // [hi|lo|hi]
}

// ---------------- mma.sync bf16 NT GEMM over KC=3072 ----------------
// CTA 128x128, 8 warps (2m x 4n), warp tile 64x32, BK=32, double buffered.
// Smem rows padded to 40 elems (80B) -> conflict-free ldmatrix.
#define SM_STRIDE 40
#define SM_TILE   (128 * SM_STRIDE * 2)        // 10240 bytes per operand tile
#define NKSTEP    (KC / 32)                    // 96

__global__ __launch_bounds__(256)
void gemm_mma_kernel(const __nv_bfloat16* __restrict__ A,
                     const __nv_bfloat16* __restrict__ B0,
                     const __nv_bfloat16* __restrict__ B1,
                     const __nv_bfloat16* __restrict__ B2,
                     float* __restrict__ C0, float* __restrict__ C1,
                     float* __restrict__ C2)
{
    __shared__ __align__(16) char smc[4 * SM_TILE];   // A0,B0,A1,B1

    int z = blockIdx.z;
    const __nv_bfloat16* B = (z == 0) ? B0 : (z == 1) ? B1 : B2;
    float* C = (z == 0) ? C0 : (z == 1) ? C1 : C2;

    const int tid = threadIdx.x;
    const int wid = tid >> 5;
    const int lane = tid & 31;
    const int warp_m = wid & 1;        // 0..1
    const int warp_n = wid >> 1;       // 0..3
    const int bm = blockIdx.y * 128;
    const int bn = blockIdx.x * 128;

    const uint32_t smem_base = smem_to_u32(smc);

    // global load pointers: each thread loads 2x16B per operand per step
    const int grow = tid >> 2;            // 0..63
    const int gchunk = (tid & 3) * 8;     // 0,8,16,24
    const __nv_bfloat16* Ag0 = A + (size_t)(bm + grow) * KC + gchunk;
    const __nv_bfloat16* Ag1 = Ag0 + (size_t)64 * KC;
    const __nv_bfloat16* Bg0 = B + (size_t)(bn + grow) * KC + gchunk;
    const __nv_bfloat16* Bg1 = Bg0 + (size_t)64 * KC;

    // smem store byte offsets (within one operand tile)
    const uint32_t soff0 = (uint32_t)(grow * SM_STRIDE + gchunk) * 2;
    const uint32_t soff1 = (uint32_t)((grow + 64) * SM_STRIDE + gchunk) * 2;

    // ldmatrix per-lane base byte offsets
    const uint32_t a_off = (uint32_t)((warp_m * 64 + (lane & 15)) * SM_STRIDE
                                      + (lane >> 4) * 8) * 2;
    const int bl = lane & 15;
    const uint32_t b_off = (uint32_t)((warp_n * 32 + (bl & 7)) * SM_STRIDE
                                      + ((bl >> 3) & 1) * 8) * 2;

    float acc[4][4][4];
    #pragma unroll
    for (int im = 0; im < 4; im++)
        #pragma unroll
        for (int in = 0; in < 4; in++)
            #pragma unroll
            for (int r = 0; r < 4; r++) acc[im][in][r] = 0.f;

    // prologue: stage 0 into buf 0
    {
        uint4 va0 = *(const uint4*)(Ag0);
        uint4 va1 = *(const uint4*)(Ag1);
        uint4 vb0 = *(const uint4*)(Bg0);
        uint4 vb1 = *(const uint4*)(Bg1);
        *(uint4*)(smc + soff0) = va0;
        *(uint4*)(smc + soff1) = va1;
        *(uint4*)(smc + SM_TILE + soff0) = vb0;
        *(uint4*)(smc + SM_TILE + soff1) = vb1;
    }
    __syncthreads();

    int buf = 0;
    for (int c = 0; c < NKSTEP; c++) {
        bool has_next = (c + 1 < NKSTEP);
        uint4 va0, va1, vb0, vb1;
        if (has_next) {
            int ko = (c + 1) * 32;
            va0 = *(const uint4*)(Ag0 + ko);
            va1 = *(const uint4*)(Ag1 + ko);
            vb0 = *(const uint4*)(Bg0 + ko);
            vb1 = *(const uint4*)(Bg1 + ko);
        }

        uint32_t Asmb = smem_base + buf * (2 * SM_TILE);
        uint32_t Bsmb = Asmb + SM_TILE;

        #pragma unroll
        for (int ik = 0; ik < 2; ik++) {
            uint32_t af[4][4];
            uint32_t bfr[4][2];
            #pragma unroll
            for (int im = 0; im < 4; im++)
                ldsm_x4(af[im], Asmb + a_off + (uint32_t)(im * 16 * SM_STRIDE + ik * 16) * 2);
            #pragma unroll
            for (int in = 0; in < 4; in++)
                ldsm_x2(bfr[in], Bsmb + b_off + (uint32_t)(in * 8 * SM_STRIDE + ik * 16) * 2);
            #pragma unroll
            for (int im = 0; im < 4; im++)
                #pragma unroll
                for (int in = 0; in < 4; in++)
                    mma16816(acc[im][in], af[im], bfr[in]);
        }

        if (has_next) {
            char* dst = smc + (buf ^ 1) * (2 * SM_TILE);
            *(uint4*)(dst + soff0) = va0;
            *(uint4*)(dst + soff1) = va1;
            *(uint4*)(dst + SM_TILE + soff0) = vb0;
            *(uint4*)(dst + SM_TILE + soff1) = vb1;
            __syncthreads();
            buf ^= 1;
        }
    }

    // epilogue
    const int g = lane >> 2, t = lane & 3;
    #pragma unroll
    for (int im = 0; im < 4; im++) {
        int r0 = bm + warp_m * 64 + im * 16 + g;
        #pragma unroll
        for (int in = 0; in < 4; in++) {
            int c0 = bn + warp_n * 32 + in * 8 + t * 2;
            float2 lo = make_float2(acc[im][in][0], acc[im][in][1]);
            float2 hi = make_float2(acc[im][in][2], acc[im][in][3]);
            *(float2*)(C + (size_t)r0 * GN + c0) = lo;
            *(float2*)(C + (size_t)(r0 + 8) * GN + c0) = hi;
        }
    }
}

// ---------------- RoPE (in-place, optional pre-scale) ----------------
__global__ __launch_bounds__(256)
void rope_kernel(float* __restrict__ x, float scale)
{
    int p = blockIdx.x * blockDim.x + threadIdx.x;
    int pd  = p & 511;
    int row = p >> 9;
    int tok = row & (NTOK - 1);
    int i   = pd & 31;

    float inv = g_invfreq[i];
    float ang = (float)tok * inv;
    float s, c;
    sincosf(ang, &s, &c);

    float* px = x + (size_t)row * DIM + 2 * pd;
    float x0 = px[0] * scale, x1 = px[1] * scale;
    px[0] = x0 * c - x1 * s;
    px[1] = x1 * c + x0 * s;
}

// ---------------- Causal flash attention (fp32), split epilogue -------------
__global__ __launch_bounds__(128)
void attn_kernel(const float* __restrict__ q, const float* __restrict__ k,
                 const float* __restrict__ v)
{
    extern __shared__ float sm[];
    float* Ks = sm;
    float* Vs = sm + 64 * 64;
    float* S  = sm + 2 * 64 * 64;   // 128*65 padded

    int bh = blockIdx.y;
    int b = bh >> 4, h = bh & 15;
    const size_t base = (size_t)b * NTOK * DIM + (size_t)h * DHEAD;
    int tid = threadIdx.x;
    int qrow = blockIdx.x * 128 + tid;

    float qreg[64];
    #pragma unroll
    for (int t = 0; t < 16; t++) {
        float4 q4 = *(const float4*)(q + base + (size_t)qrow * DIM + t * 4);
        qreg[t * 4 + 0] = q4.x; qreg[t * 4 + 1] = q4.y;
        qreg[t * 4 + 2] = q4.z; qreg[t * 4 + 3] = q4.w;
    }

    float m = -1e30f, l = 0.f;
    float oa[64];
    #pragma unroll
    for (int t = 0; t < 64; t++) oa[t] = 0.f;

    int kend = blockIdx.x * 128 + 128;
    int lr = tid >> 1;
    int lc = (tid & 1) * 32;

    for (int j0 = 0; j0 < kend; j0 += 64) {
        __syncthreads();
        #pragma unroll
        for (int t = 0; t < 8; t++) {
            *(float4*)&Ks[lr * 64 + lc + t * 4] =
                *(const float4*)(k + base + (size_t)(j0 + lr) * DIM + lc + t * 4);
            *(float4*)&Vs[lr * 64 + lc + t * 4] =
                *(const float4*)(v + base + (size_t)(j0 + lr) * DIM + lc + t * 4);
        }
        __syncthreads();

        int jmax = qrow - j0 + 1;
        if (jmax > 64) jmax = 64;

        float mt = -1e30f;
        for (int j = 0; j < 64; j++) {
            const float4* kr = (const float4*)&Ks[j * 64];
            float s = 0.f;
            #pragma unroll
            for (int t = 0; t < 16; t++) {
                float4 k4 = kr[t];
                s += qreg[t * 4 + 0] * k4.x + qreg[t * 4 + 1] * k4.y
                   + qreg[t * 4 + 2] * k4.z + qreg[t * 4 + 3] * k4.w;
            }
            s = (j < jmax) ? s : -1e30f;
            S[tid * 65 + j] = s;
            mt = fmaxf(mt, s);
        }

        float mnew = fmaxf(m, mt);
        float alpha = __expf(m - mnew);
        l *= alpha;
        #pragma unroll
        for (int t = 0; t < 64; t++) oa[t] *= alpha;
        m = mnew;

        for (int j = 0; j < 64; j++) {
            float p = __expf(S[tid * 65 + j] - mnew);
            l += p;
            const float4* vr = (const float4*)&Vs[j * 64];
            #pragma unroll
            for (int t = 0; t < 16; t++) {
                float4 v4 = vr[t];
                oa[t * 4 + 0] += p * v4.x; oa[t * 4 + 1] += p * v4.y;
                oa[t * 4 + 2] += p * v4.z; oa[t * 4 + 3] += p * v4.w;
            }
        }
    }

    float inv = 1.f / l;
    __nv_bfloat16* acb = g_ac + (size_t)(b * NTOK + qrow) * KC + h * 64;
    #pragma unroll
    for (int t = 0; t < 16; t++) {
        float4 o4 = make_float4(oa[t * 4 + 0] * inv, oa[t * 4 + 1] * inv,
                                oa[t * 4 + 2] * inv, oa[t * 4 + 3] * inv);
        int col = t * 4;
        split_store4(acb + col, acb + 1024 + col, acb + 2048 + col, o4);  // [hi|hi|lo]
    }
}

// ---------------- launch ----------------
extern "C" void kernel_launch(void* const* d_in, const int* in_sizes, int n_in,
                              void* d_out, int out_size)
{
    const float* tokens = (const float*)d_in[0];
    const float* nw     = (const float*)d_in[1];
    const float* wq     = (const float*)d_in[2];
    const float* wk     = (const float*)d_in[3];
    const float* wv     = (const float*)d_in[4];
    const float* wo     = (const float*)d_in[5];
    float* out = (float*)d_out;

    float *qb, *kb, *vb;
    __nv_bfloat16 *xc, *ac, *wc;
    cudaGetSymbolAddress((void**)&qb, g_q);
    cudaGetSymbolAddress((void**)&kb, g_k);
    cudaGetSymbolAddress((void**)&vb, g_v);
    cudaGetSymbolAddress((void**)&xc, g_xc);
    cudaGetSymbolAddress((void**)&ac, g_ac);
    cudaGetSymbolAddress((void**)&wc, g_wc);

    init_invfreq_kernel<<<1, 32>>>();
    convert_w_kernel<<<dim3(1024, 1, 4), 256>>>(wq, wk, wv, wo);
    rmsnorm_split_kernel<<<NROWS, 256>>>(tokens, nw);

    // QKV: one fused mma.sync launch (768 CTAs)
    gemm_mma_kernel<<<dim3(8, 32, 3), 256>>>(
        xc, wc, wc + WSZ, wc + 2 * WSZ, qb, kb, vb);

    int pairs = NROWS * DIM / 2;
    rope_kernel<<<pairs / 256, 256>>>(qb, 0.125f);   // 64^-0.5 folded in
    rope_kernel<<<pairs / 256, 256>>>(kb, 1.0f);

    const int ATTN_SMEM = (2 * 64 * 64 + 128 * 65) * (int)sizeof(float);
    cudaFuncSetAttribute(attn_kernel, cudaFuncAttributeMaxDynamicSharedMemorySize, ATTN_SMEM);
    attn_kernel<<<dim3(NTOK / 128, NB * NHEADS), 128, ATTN_SMEM>>>(qb, kb, vb);

    // Output projection
    gemm_mma_kernel<<<dim3(8, 32, 1), 256>>>(
        ac, wc + 3 * WSZ, wc + 3 * WSZ, wc + 3 * WSZ, out, out, out);
}

// round 11
// speedup vs baseline: 2.7125x; 2.2728x over previous
#include <cuda_runtime.h>
#include <cuda_bf16.h>
#include <math.h>
#include <stdint.h>

#define DIM    1024
#define NHEADS 16
#define DHEAD  64
#define NTOK   2048
#define NB     2
#define NROWS  (NB * NTOK)   // 4096
#define KC     3072          // tripled K for hi/lo split GEMM
#define WSZ    (1024 * KC)
#define GN     1024

// ---------------- scratch (no allocations allowed) ----------------
__device__ float g_q[NROWS * DIM];
__device__ float g_k[NROWS * DIM];
__device__ float g_v[NROWS * DIM];
__device__ __align__(16) __nv_bfloat16 g_xc[NROWS * KC];   // x norm, split [hi|hi|lo]
__device__ __align__(16) __nv_bfloat16 g_ac[NROWS * KC];   // attn out, split [hi|hi|lo]
__device__ __align__(16) __nv_bfloat16 g_wc[4 * WSZ];      // weights split [hi|lo|hi]
__device__ __align__(16) __nv_bfloat16 g_qh[NROWS * DIM], g_ql[NROWS * DIM];
__device__ __align__(16) __nv_bfloat16 g_kh[NROWS * DIM], g_kl[NROWS * DIM];
__device__ __align__(16) __nv_bfloat16 g_vth[NB * NHEADS * DHEAD * NTOK];
__device__ __align__(16) __nv_bfloat16 g_vtl[NB * NHEADS * DHEAD * NTOK];
__device__ float g_invfreq[32];

// ================= PTX helpers (non-'a' features only) =================
__device__ __forceinline__ uint32_t smem_to_u32(const void* p) {
    uint32_t a;
    asm("{ .reg .u64 t; cvta.to.shared.u64 t, %1; cvt.u32.u64 %0, t; }" : "=r"(a) : "l"(p));
    return a;
}
__device__ __forceinline__ void ldsm_x4(uint32_t* r, uint32_t addr) {
    asm volatile("ldmatrix.sync.aligned.m8n8.x4.shared.b16 {%0,%1,%2,%3}, [%4];"
        : "=r"(r[0]), "=r"(r[1]), "=r"(r[2]), "=r"(r[3]) : "r"(addr));
}
__device__ __forceinline__ void ldsm_x2(uint32_t* r, uint32_t addr) {
    asm volatile("ldmatrix.sync.aligned.m8n8.x2.shared.b16 {%0,%1}, [%2];"
        : "=r"(r[0]), "=r"(r[1]) : "r"(addr));
}
__device__ __forceinline__ void mma16816(float* d, const uint32_t* a, const uint32_t* b) {
    asm volatile(
        "mma.sync.aligned.m16n8k16.row.col.f32.bf16.bf16.f32 "
        "{%0,%1,%2,%3}, {%4,%5,%6,%7}, {%8,%9}, {%0,%1,%2,%3};"
        : "+f"(d[0]), "+f"(d[1]), "+f"(d[2]), "+f"(d[3])
        : "r"(a[0]), "r"(a[1]), "r"(a[2]), "r"(a[3]), "r"(b[0]), "r"(b[1]));
}
__device__ __forceinline__ uint32_t pack_bf2(float x, float y) {
    __nv_bfloat162 p = __halves2bfloat162(__float2bfloat16(x), __float2bfloat16(y));
    uint32_t u; *(__nv_bfloat162*)&u = p; return u;
}

// ---------------- hi/lo split helpers ----------------
__device__ __forceinline__ void split_store4(__nv_bfloat16* p_hi1, __nv_bfloat16* p_hi2,
                                             __nv_bfloat16* p_lo, float4 v)
{
    __nv_bfloat16 h0 = __float2bfloat16(v.x), h1 = __float2bfloat16(v.y);
    __nv_bfloat16 h2 = __float2bfloat16(v.z), h3 = __float2bfloat16(v.w);
    __nv_bfloat16 l0 = __float2bfloat16(v.x - __bfloat162float(h0));
    __nv_bfloat16 l1 = __float2bfloat16(v.y - __bfloat162float(h1));
    __nv_bfloat16 l2 = __float2bfloat16(v.z - __bfloat162float(h2));
    __nv_bfloat16 l3 = __float2bfloat16(v.w - __bfloat162float(h3));
    __nv_bfloat162 ha = __halves2bfloat162(h0, h1), hb = __halves2bfloat162(h2, h3);
    __nv_bfloat162 la = __halves2bfloat162(l0, l1), lb = __halves2bfloat162(l2, l3);
    *(__nv_bfloat162*)(p_hi1) = ha; *(__nv_bfloat162*)(p_hi1 + 2) = hb;
    *(__nv_bfloat162*)(p_hi2) = ha; *(__nv_bfloat162*)(p_hi2 + 2) = hb;
    *(__nv_bfloat162*)(p_lo)  = la; *(__nv_bfloat162*)(p_lo + 2)  = lb;
}
__device__ __forceinline__ void split_store2(__nv_bfloat16* p_hi1, __nv_bfloat16* p_hi2,
                                             __nv_bfloat16* p_lo, float v0, float v1)
{
    __nv_bfloat16 h0 = __float2bfloat16(v0), h1 = __float2bfloat16(v1);
    __nv_bfloat16 l0 = __float2bfloat16(v0 - __bfloat162float(h0));
    __nv_bfloat16 l1 = __float2bfloat16(v1 - __bfloat162float(h1));
    __nv_bfloat162 ha = __halves2bfloat162(h0, h1);
    __nv_bfloat162 la = __halves2bfloat162(l0, l1);
    *(__nv_bfloat162*)(p_hi1) = ha;
    *(__nv_bfloat162*)(p_hi2) = ha;
    *(__nv_bfloat162*)(p_lo)  = la;
}

// ---------------- inv_freq table ----------------
__global__ void init_invfreq_kernel()
{
    int i = threadIdx.x;
    g_invfreq[i] = (float)(1.0 / pow(10000.0, (double)(2 * i) / 64.0));
}

// ---------------- RMSNorm fused with split-conversion ----------------
__global__ __launch_bounds__(256)
void rmsnorm_split_kernel(const float* __restrict__ x, const float* __restrict__ w)
{
    int row = blockIdx.x;
    const float* xr = x + (size_t)row * DIM;
    int tid = threadIdx.x;

    float4 v = ((const float4*)xr)[tid];
    float ss = v.x * v.x + v.y * v.y + v.z * v.z + v.w * v.w;
    #pragma unroll
    for (int o = 16; o > 0; o >>= 1) ss += __shfl_xor_sync(0xffffffffu, ss, o);

    __shared__ float warpsum[8];
    __shared__ float rstd_s;
    if ((tid & 31) == 0) warpsum[tid >> 5] = ss;
    __syncthreads();
    if (tid == 0) {
        float t = 0.f;
        #pragma unroll
        for (int i = 0; i < 8; i++) t += warpsum[i];
        rstd_s = rsqrtf(t * (1.0f / DIM) + 1.1920929e-07f);
    }
    __syncthreads();
    float rstd = rstd_s;

    float4 wv = ((const float4*)w)[tid];
    float4 o4 = make_float4(v.x * rstd * wv.x, v.y * rstd * wv.y,
                            v.z * rstd * wv.z, v.w * rstd * wv.w);
    __nv_bfloat16* base = g_xc + (size_t)row * KC;
    int col = tid * 4;
    split_store4(base + col, base + 1024 + col, base + 2048 + col, o4);  // [hi|hi|lo]
}

// ---------------- weight split-conversion: [hi | lo | hi] ----------------
__global__ __launch_bounds__(256)
void convert_w_kernel(const float* __restrict__ w0, const float* __restrict__ w1,
                      const float* __restrict__ w2, const float* __restrict__ w3)
{
    int z = blockIdx.z;
    const float* w = (z == 0) ? w0 : (z == 1) ? w1 : (z == 2) ? w2 : w3;
    int p = blockIdx.x * 256 + threadIdx.x;
    int row = p >> 8;
    int c4 = (p & 255) * 4;
    float4 v = *(const float4*)(w + (size_t)row * 1024 + c4);
    __nv_bfloat16* base = g_wc + (size_t)z * WSZ + (size_t)row * KC;
    split_store4(base + c4, base + 2048 + c4, base + 1024 + c4, v);      // [hi|lo|hi]
}

// ---------------- mma.sync bf16 NT GEMM over KC=3072 (unchanged, passing) ---
#define SM_STRIDE 40
#define SM_TILE   (128 * SM_STRIDE * 2)
#define NKSTEP    (KC / 32)

__global__ __launch_bounds__(256)
void gemm_mma_kernel(const __nv_bfloat16* __restrict__ A,
                     const __nv_bfloat16* __restrict__ B0,
                     const __nv_bfloat16* __restrict__ B1,
                     const __nv_bfloat16* __restrict__ B2,
                     float* __restrict__ C0, float* __restrict__ C1,
                     float* __restrict__ C2)
{
    __shared__ __align__(16) char smc[4 * SM_TILE];

    int z = blockIdx.z;
    const __nv_bfloat16* B = (z == 0) ? B0 : (z == 1) ? B1 : B2;
    float* C = (z == 0) ? C0 : (z == 1) ? C1 : C2;

    const int tid = threadIdx.x;
    const int wid = tid >> 5;
    const int lane = tid & 31;
    const int warp_m = wid & 1;
    const int warp_n = wid >> 1;
    const int bm = blockIdx.y * 128;
    const int bn = blockIdx.x * 128;

    const uint32_t smem_base = smem_to_u32(smc);

    const int grow = tid >> 2;
    const int gchunk = (tid & 3) * 8;
    const __nv_bfloat16* Ag0 = A + (size_t)(bm + grow) * KC + gchunk;
    const __nv_bfloat16* Ag1 = Ag0 + (size_t)64 * KC;
    const __nv_bfloat16* Bg0 = B + (size_t)(bn + grow) * KC + gchunk;
    const __nv_bfloat16* Bg1 = Bg0 + (size_t)64 * KC;

    const uint32_t soff0 = (uint32_t)(grow * SM_STRIDE + gchunk) * 2;
    const uint32_t soff1 = (uint32_t)((grow + 64) * SM_STRIDE + gchunk) * 2;

    const uint32_t a_off = (uint32_t)((warp_m * 64 + (lane & 15)) * SM_STRIDE
                                      + (lane >> 4) * 8) * 2;
    const int bl = lane & 15;
    const uint32_t b_off = (uint32_t)((warp_n * 32 + (bl & 7)) * SM_STRIDE
                                      + ((bl >> 3) & 1) * 8) * 2;

    float acc[4][4][4];
    #pragma unroll
    for (int im = 0; im < 4; im++)
        #pragma unroll
        for (int in = 0; in < 4; in++)
            #pragma unroll
            for (int r = 0; r < 4; r++) acc[im][in][r] = 0.f;

    {
        uint4 va0 = *(const uint4*)(Ag0);
        uint4 va1 = *(const uint4*)(Ag1);
        uint4 vb0 = *(const uint4*)(Bg0);
        uint4 vb1 = *(const uint4*)(Bg1);
        *(uint4*)(smc + soff0) = va0;
        *(uint4*)(smc + soff1) = va1;
        *(uint4*)(smc + SM_TILE + soff0) = vb0;
        *(uint4*)(smc + SM_TILE + soff1) = vb1;
    }
    __syncthreads();

    int buf = 0;
    for (int c = 0; c < NKSTEP; c++) {
        bool has_next = (c + 1 < NKSTEP);
        uint4 va0, va1, vb0, vb1;
        if (has_next) {
            int ko = (c + 1) * 32;
            va0 = *(const uint4*)(Ag0 + ko);
            va1 = *(const uint4*)(Ag1 + ko);
            vb0 = *(const uint4*)(Bg0 + ko);
            vb1 = *(const uint4*)(Bg1 + ko);
        }

        uint32_t Asmb = smem_base + buf * (2 * SM_TILE);
        uint32_t Bsmb = Asmb + SM_TILE;

        #pragma unroll
        for (int ik = 0; ik < 2; ik++) {
            uint32_t af[4][4];
            uint32_t bfr[4][2];
            #pragma unroll
            for (int im = 0; im < 4; im++)
                ldsm_x4(af[im], Asmb + a_off + (uint32_t)(im * 16 * SM_STRIDE + ik * 16) * 2);
            #pragma unroll
            for (int in = 0; in < 4; in++)
                ldsm_x2(bfr[in], Bsmb + b_off + (uint32_t)(in * 8 * SM_STRIDE + ik * 16) * 2);
            #pragma unroll
            for (int im = 0; im < 4; im++)
                #pragma unroll
                for (int in = 0; in < 4; in++)
                    mma16816(acc[im][in], af[im], bfr[in]);
        }

        if (has_next) {
            char* dst = smc + (buf ^ 1) * (2 * SM_TILE);
            *(uint4*)(dst + soff0) = va0;
            *(uint4*)(dst + soff1) = va1;
            *(uint4*)(dst + SM_TILE + soff0) = vb0;
            *(uint4*)(dst + SM_TILE + soff1) = vb1;
            __syncthreads();
            buf ^= 1;
        }
    }

    const int g = lane >> 2, t = lane & 3;
    #pragma unroll
    for (int im = 0; im < 4; im++) {
        int r0 = bm + warp_m * 64 + im * 16 + g;
        #pragma unroll
        for (int in = 0; in < 4; in++) {
            int c0 = bn + warp_n * 32 + in * 8 + t * 2;
            float2 lo = make_float2(acc[im][in][0], acc[im][in][1]);
            float2 hi = make_float2(acc[im][in][2], acc[im][in][3]);
            *(float2*)(C + (size_t)r0 * GN + c0) = lo;
            *(float2*)(C + (size_t)(r0 + 8) * GN + c0) = hi;
        }
    }
}

// ---------------- RoPE + hi/lo split to bf16 ----------------
__global__ __launch_bounds__(256)
void rope_split_kernel(const float* __restrict__ x, __nv_bfloat16* __restrict__ xh,
                       __nv_bfloat16* __restrict__ xl, float scale)
{
    int p = blockIdx.x * blockDim.x + threadIdx.x;
    int pd  = p & 511;
    int row = p >> 9;
    int tok = row & (NTOK - 1);
    int i   = pd & 31;

    float inv = g_invfreq[i];
    float ang = (float)tok * inv;
    float s, c;
    sincosf(ang, &s, &c);

    const float* px = x + (size_t)row * DIM + 2 * pd;
    float x0 = px[0] * scale, x1 = px[1] * scale;
    float r0 = x0 * c - x1 * s;
    float r1 = x1 * c + x0 * s;

    __nv_bfloat16 h0 = __float2bfloat16(r0), h1 = __float2bfloat16(r1);
    __nv_bfloat16 l0 = __float2bfloat16(r0 - __bfloat162float(h0));
    __nv_bfloat16 l1 = __float2bfloat16(r1 - __bfloat162float(h1));
    size_t off = (size_t)row * DIM + 2 * pd;
    *(__nv_bfloat162*)(xh + off) = __halves2bfloat162(h0, h1);
    *(__nv_bfloat162*)(xl + off) = __halves2bfloat162(l0, l1);
}

// ---------------- V transpose + split: [b,tok,h*64+d] -> [b,h,d,tok] --------
__global__ __launch_bounds__(256)
void v_split_tr_kernel(const float* __restrict__ v)
{
    __shared__ float st[64][65];
    int bh = blockIdx.y, b = bh >> 4, h = bh & 15;
    int t0 = blockIdx.x * 64;
    int tid = threadIdx.x;

    #pragma unroll
    for (int u = 0; u < 16; u++) {
        int idx = tid + u * 256;
        int row = idx >> 6, col = idx & 63;
        st[row][col] = v[(size_t)(b * NTOK + t0 + row) * DIM + h * 64 + col];
    }
    __syncthreads();

    int d = tid >> 2, ch = (tid & 3) * 16;
    size_t obase = ((size_t)bh * 64 + d) * NTOK + t0 + ch;
    #pragma unroll
    for (int i = 0; i < 16; i++) {
        float val = st[ch + i][d];
        __nv_bfloat16 hi = __float2bfloat16(val);
        __nv_bfloat16 lo = __float2bfloat16(val - __bfloat162float(hi));
        g_vth[obase + i] = hi;
        g_vtl[obase + i] = lo;
    }
}

// ---------------- Tensor-core causal flash attention (hi/lo split) ----------
// CTA: 128 thr (4 warps x 16 q-rows = 64-row tile). grid (NTOK/64, NB*NHEADS).
#define AST 72   // smem row stride (elems); 16B-ldsm conflict-free

__global__ __launch_bounds__(128)
void attn_mma_kernel(const __nv_bfloat16* __restrict__ qh, const __nv_bfloat16* __restrict__ ql,
                     const __nv_bfloat16* __restrict__ kh, const __nv_bfloat16* __restrict__ kl)
{
    __shared__ __align__(16) char smraw[4 * 64 * AST * 2];   // 36864B
    const uint32_t smb = smem_to_u32(smraw);

    int tid = threadIdx.x, w = tid >> 5, lane = tid & 31;
    int g = lane >> 2, t = lane & 3, bl = lane & 15;
    int bh = blockIdx.y, b = bh >> 4, h = bh & 15;
    int qbase = blockIdx.x * 64;

    // ---- stage Q (hi @0, lo @64*AST) ----
    #pragma unroll
    for (int u = 0; u < 8; u++) {
        int cid = tid + u * 128;                 // 0..1023
        int arr = cid >> 9, rem = cid & 511, row = rem >> 3, ci = rem & 7;
        const __nv_bfloat16* src = (arr ? ql : qh)
            + (size_t)(b * NTOK + qbase + row) * DIM + h * 64 + ci * 8;
        *(uint4*)(smraw + (arr * 64 * AST + row * AST + ci * 8) * 2) = *(const uint4*)src;
    }
    __syncthreads();

    uint32_t qfh[4][4], qfl[4][4];
    {
        uint32_t abase = smb + (uint32_t)((w * 16 + bl) * AST + (lane >> 4) * 8) * 2;
        #pragma unroll
        for (int kk = 0; kk < 4; kk++) {
            ldsm_x4(qfh[kk], abase + kk * 32);
            ldsm_x4(qfl[kk], abase + 64 * AST * 2 + kk * 32);
        }
    }
    __syncthreads();

    float O[8][4];
    #pragma unroll
    for (int nn = 0; nn < 8; nn++)
        #pragma unroll
        for (int r = 0; r < 4; r++) O[nn][r] = 0.f;
    float m0 = -1e30f, m1 = -1e30f, l0 = 0.f, l1 = 0.f;
    const int wmin = qbase + w * 16;
    const int r0g = wmin + g, r1g = r0g + 8;

    for (int j0 = 0; j0 <= qbase; j0 += 64) {
        // ---- load K(hi,lo) rows=keys and Vt(hi,lo) rows=dims ----
        #pragma unroll
        for (int u = 0; u < 16; u++) {
            int cid = tid + u * 128;             // 0..2047
            int tile = cid >> 9, rem = cid & 511, row = rem >> 3, ci = rem & 7;
            const __nv_bfloat16* src;
            if (tile == 0)      src = kh + (size_t)(b * NTOK + j0 + row) * DIM + h * 64 + ci * 8;
            else if (tile == 1) src = kl + (size_t)(b * NTOK + j0 + row) * DIM + h * 64 + ci * 8;
            else if (tile == 2) src = g_vth + ((size_t)bh * 64 + row) * NTOK + j0 + ci * 8;
            else                src = g_vtl + ((size_t)bh * 64 + row) * NTOK + j0 + ci * 8;
            *(uint4*)(smraw + (tile * 64 * AST + row * AST + ci * 8) * 2) = *(const uint4*)src;
        }
        __syncthreads();

        // ---- S = Q K^T (3-term split) ----
        float S[8][4];
        #pragma unroll
        for (int nn = 0; nn < 8; nn++)
            #pragma unroll
            for (int r = 0; r < 4; r++) S[nn][r] = 0.f;

        const uint32_t kboff = smb + (uint32_t)((bl & 7) * AST + ((bl >> 3) & 1) * 8) * 2;
        #pragma unroll
        for (int nn = 0; nn < 8; nn++) {
            #pragma unroll
            for (int kk = 0; kk < 4; kk++) {
                uint32_t kfh[2], kfl[2];
                uint32_t ad = kboff + (uint32_t)(nn * 8 * AST) * 2 + kk * 32;
                ldsm_x2(kfh, ad);
                ldsm_x2(kfl, ad + 64 * AST * 2);
                mma16816(S[nn], qfh[kk], kfh);
                mma16816(S[nn], qfh[kk], kfl);
                mma16816(S[nn], qfl[kk], kfh);
            }
        }

        // ---- causal mask (diagonal tile only) ----
        if (j0 + 63 > wmin) {
            #pragma unroll
            for (int nn = 0; nn < 8; nn++) {
                int jg = j0 + nn * 8 + 2 * t;
                if (jg     > r0g) S[nn][0] = -1e30f;
                if (jg + 1 > r0g) S[nn][1] = -1e30f;
                if (jg     > r1g) S[nn][2] = -1e30f;
                if (jg + 1 > r1g) S[nn][3] = -1e30f;
            }
        }

        // ---- online softmax ----
        float mt0 = -1e30f, mt1 = -1e30f;
        #pragma unroll
        for (int nn = 0; nn < 8; nn++) {
            mt0 = fmaxf(mt0, fmaxf(S[nn][0], S[nn][1]));
            mt1 = fmaxf(mt1, fmaxf(S[nn][2], S[nn][3]));
        }
        mt0 = fmaxf(mt0, __shfl_xor_sync(0xffffffffu, mt0, 1));
        mt0 = fmaxf(mt0, __shfl_xor_sync(0xffffffffu, mt0, 2));
        mt1 = fmaxf(mt1, __shfl_xor_sync(0xffffffffu, mt1, 1));
        mt1 = fmaxf(mt1, __shfl_xor_sync(0xffffffffu, mt1, 2));

        float mnew0 = fmaxf(m0, mt0), mnew1 = fmaxf(m1, mt1);
        float alpha0 = __expf(m0 - mnew0), alpha1 = __expf(m1 - mnew1);
        m0 = mnew0; m1 = mnew1;

        float rs0 = 0.f, rs1 = 0.f;
        uint32_t ah[4][4], al[4][4];
        #pragma unroll
        for (int nn = 0; nn < 8; nn++) {
            float p0 = __expf(S[nn][0] - mnew0);
            float p1 = __expf(S[nn][1] - mnew0);
            float p2 = __expf(S[nn][2] - mnew1);
            float p3 = __expf(S[nn][3] - mnew1);
            rs0 += p0 + p1; rs1 += p2 + p3;
            float h0 = __bfloat162float(__float2bfloat16(p0));
            float h1 = __bfloat162float(__float2bfloat16(p1));
            float h2 = __bfloat162float(__float2bfloat16(p2));
            float h3 = __bfloat162float(__float2bfloat16(p3));
            int kk = nn >> 1, pt = (nn & 1) * 2;
            ah[kk][pt]     = pack_bf2(h0, h1);
            ah[kk][pt + 1] = pack_bf2(h2, h3);
            al[kk][pt]     = pack_bf2(p0 - h0, p1 - h1);
            al[kk][pt + 1] = pack_bf2(p2 - h2, p3 - h3);
        }
        rs0 += __shfl_xor_sync(0xffffffffu, rs0, 1);
        rs0 += __shfl_xor_sync(0xffffffffu, rs0, 2);
        rs1 += __shfl_xor_sync(0xffffffffu, rs1, 1);
        rs1 += __shfl_xor_sync(0xffffffffu, rs1, 2);
        l0 = l0 * alpha0 + rs0;
        l1 = l1 * alpha1 + rs1;

        #pragma unroll
        for (int nn = 0; nn < 8; nn++) {
            O[nn][0] *= alpha0; O[nn][1] *= alpha0;
            O[nn][2] *= alpha1; O[nn][3] *= alpha1;
        }

        // ---- O += P Vt (3-term split). Vt tiles at smem sections 2,3 ----
        const uint32_t vboff = smb + (uint32_t)(2 * 64 * AST) * 2
                             + (uint32_t)((bl & 7) * AST + ((bl >> 3) & 1) * 8) * 2;
        #pragma unroll
        for (int nn = 0; nn < 8; nn++) {
            #pragma unroll
            for (int kk = 0; kk < 4; kk++) {
                uint32_t vfh[2], vfl[2];
                uint32_t ad = vboff + (uint32_t)(nn * 8 * AST) * 2 + kk * 32;
                ldsm_x2(vfh, ad);
                ldsm_x2(vfl, ad + 64 * AST * 2);
                mma16816(O[nn], ah[kk], vfh);
                mma16816(O[nn], ah[kk], vfl);
                mma16816(O[nn], al[kk], vfh);
            }
        }
        __syncthreads();
    }

    // ---- epilogue: normalize + split-store to g_ac [hi|hi|lo] ----
    float inv0 = 1.f / l0, inv1 = 1.f / l1;
    __nv_bfloat16* ac0 = g_ac + (size_t)(b * NTOK + r0g) * KC;
    __nv_bfloat16* ac1 = g_ac + (size_t)(b * NTOK + r1g) * KC;
    #pragma unroll
    for (int nn = 0; nn < 8; nn++) {
        int col = h * 64 + nn * 8 + 2 * t;
        split_store2(ac0 + col, ac0 + 1024 + col, ac0 + 2048 + col,
                     O[nn][0] * inv0, O[nn][1] * inv0);
        split_store2(ac1 + col, ac1 + 1024 + col, ac1 + 2048 + col,
                     O[nn][2] * inv1, O[nn][3] * inv1);
    }
}

// ---------------- launch ----------------
extern "C" void kernel_launch(void* const* d_in, const int* in_sizes, int n_in,
                              void* d_out, int out_size)
{
    const float* tokens = (const float*)d_in[0];
    const float* nw     = (const float*)d_in[1];
    const float* wq     = (const float*)d_in[2];
    const float* wk     = (const float*)d_in[3];
    const float* wv     = (const float*)d_in[4];
    const float* wo     = (const float*)d_in[5];
    float* out = (float*)d_out;

    float *qb, *kb, *vb;
    __nv_bfloat16 *xc, *ac, *wc, *qhp, *qlp, *khp, *klp;
    cudaGetSymbolAddress((void**)&qb, g_q);
    cudaGetSymbolAddress((void**)&kb, g_k);
    cudaGetSymbolAddress((void**)&vb, g_v);
    cudaGetSymbolAddress((void**)&xc, g_xc);
    cudaGetSymbolAddress((void**)&ac, g_ac);
    cudaGetSymbolAddress((void**)&wc, g_wc);
    cudaGetSymbolAddress((void**)&qhp, g_qh);
    cudaGetSymbolAddress((void**)&qlp, g_ql);
    cudaGetSymbolAddress((void**)&khp, g_kh);
    cudaGetSymbolAddress((void**)&klp, g_kl);

    init_invfreq_kernel<<<1, 32>>>();
    convert_w_kernel<<<dim3(1024, 1, 4), 256>>>(wq, wk, wv, wo);
    rmsnorm_split_kernel<<<NROWS, 256>>>(tokens, nw);

    // QKV: fused mma.sync launch (768 CTAs)
    gemm_mma_kernel<<<dim3(8, 32, 3), 256>>>(
        xc, wc, wc + WSZ, wc + 2 * WSZ, qb, kb, vb);

    int pairs = NROWS * DIM / 2;
    rope_split_kernel<<<pairs / 256, 256>>>(qb, qhp, qlp, 0.125f);
    rope_split_kernel<<<pairs / 256, 256>>>(kb, khp, klp, 1.0f);
    v_split_tr_kernel<<<dim3(NTOK / 64, NB * NHEADS), 256>>>(vb);

    // Tensor-core flash attention
    attn_mma_kernel<<<dim3(NTOK / 64, NB * NHEADS), 128>>>(qhp, qlp, khp, klp);

    // Output projection
    gemm_mma_kernel<<<dim3(8, 32, 1), 256>>>(
        ac, wc + 3 * WSZ, wc + 3 * WSZ, wc + 3 * WSZ, out, out, out);
}

// round 13
// speedup vs baseline: 2.9861x; 1.1009x over previous
#include <cuda_runtime.h>
#include <cuda_bf16.h>
#include <math.h>
#include <stdint.h>

#define DIM    1024
#define NHEADS 16
#define DHEAD  64
#define NTOK   2048
#define NB     2
#define NROWS  (NB * NTOK)   // 4096
#define KC2    2048          // [hi|lo] split K
#define WSZ2   (1024 * KC2)
#define GN     1024

// ---------------- scratch (no allocations allowed) ----------------
__device__ float g_q[NROWS * DIM];
__device__ float g_k[NROWS * DIM];
__device__ float g_v[NROWS * DIM];
__device__ __align__(16) __nv_bfloat16 g_xc[NROWS * KC2];  // x norm, [hi|lo]
__device__ __align__(16) __nv_bfloat16 g_ac[NROWS * KC2];  // attn out, [hi|lo]
__device__ __align__(16) __nv_bfloat16 g_wc[4 * WSZ2];     // weights, [hi|lo]
__device__ __align__(16) __nv_bfloat16 g_qh[NROWS * DIM], g_ql[NROWS * DIM];
__device__ __align__(16) __nv_bfloat16 g_kh[NROWS * DIM], g_kl[NROWS * DIM];
__device__ __align__(16) __nv_bfloat16 g_vth[NB * NHEADS * DHEAD * NTOK];
__device__ __align__(16) __nv_bfloat16 g_vtl[NB * NHEADS * DHEAD * NTOK];
__device__ float g_invfreq[32];

// ================= PTX helpers (non-'a' features only) =================
__device__ __forceinline__ uint32_t smem_to_u32(const void* p) {
    uint32_t a;
    asm("{ .reg .u64 t; cvta.to.shared.u64 t, %1; cvt.u32.u64 %0, t; }" : "=r"(a) : "l"(p));
    return a;
}
__device__ __forceinline__ void ldsm_x4(uint32_t* r, uint32_t addr) {
    asm volatile("ldmatrix.sync.aligned.m8n8.x4.shared.b16 {%0,%1,%2,%3}, [%4];"
        : "=r"(r[0]), "=r"(r[1]), "=r"(r[2]), "=r"(r[3]) : "r"(addr));
}
__device__ __forceinline__ void ldsm_x2(uint32_t* r, uint32_t addr) {
    asm volatile("ldmatrix.sync.aligned.m8n8.x2.shared.b16 {%0,%1}, [%2];"
        : "=r"(r[0]), "=r"(r[1]) : "r"(addr));
}
__device__ __forceinline__ void mma16816(float* d, const uint32_t* a, const uint32_t* b) {
    asm volatile(
        "mma.sync.aligned.m16n8k16.row.col.f32.bf16.bf16.f32 "
        "{%0,%1,%2,%3}, {%4,%5,%6,%7}, {%8,%9}, {%0,%1,%2,%3};"
        : "+f"(d[0]), "+f"(d[1]), "+f"(d[2]), "+f"(d[3])
        : "r"(a[0]), "r"(a[1]), "r"(a[2]), "r"(a[3]), "r"(b[0]), "r"(b[1]));
}
__device__ __forceinline__ uint32_t pack_bf2(float x, float y) {
    __nv_bfloat162 p = __halves2bfloat162(__float2bfloat16(x), __float2bfloat16(y));
    uint32_t u; *(__nv_bfloat162*)&u = p; return u;
}
#define CP16(dst, src) \
    asm volatile("cp.async.cg.shared.global [%0], [%1], 16;" :: "r"(dst), "l"(src))
#define CP_COMMIT() asm volatile("cp.async.commit_group;" ::: "memory")
#define CP_WAIT0()  asm volatile("cp.async.wait_group 0;" ::: "memory")

// ---------------- hi/lo split helpers ----------------
__device__ __forceinline__ void split_store4(__nv_bfloat16* p_hi, __nv_bfloat16* p_lo, float4 v)
{
    __nv_bfloat16 h0 = __float2bfloat16(v.x), h1 = __float2bfloat16(v.y);
    __nv_bfloat16 h2 = __float2bfloat16(v.z), h3 = __float2bfloat16(v.w);
    __nv_bfloat16 l0 = __float2bfloat16(v.x - __bfloat162float(h0));
    __nv_bfloat16 l1 = __float2bfloat16(v.y - __bfloat162float(h1));
    __nv_bfloat16 l2 = __float2bfloat16(v.z - __bfloat162float(h2));
    __nv_bfloat16 l3 = __float2bfloat16(v.w - __bfloat162float(h3));
    *(__nv_bfloat162*)(p_hi)     = __halves2bfloat162(h0, h1);
    *(__nv_bfloat162*)(p_hi + 2) = __halves2bfloat162(h2, h3);
    *(__nv_bfloat162*)(p_lo)     = __halves2bfloat162(l0, l1);
    *(__nv_bfloat162*)(p_lo + 2) = __halves2bfloat162(l2, l3);
}
__device__ __forceinline__ void split_store2(__nv_bfloat16* p_hi, __nv_bfloat16* p_lo,
                                             float v0, float v1)
{
    __nv_bfloat16 h0 = __float2bfloat16(v0), h1 = __float2bfloat16(v1);
    __nv_bfloat16 l0 = __float2bfloat16(v0 - __bfloat162float(h0));
    __nv_bfloat16 l1 = __float2bfloat16(v1 - __bfloat162float(h1));
    *(__nv_bfloat162*)(p_hi) = __halves2bfloat162(h0, h1);
    *(__nv_bfloat162*)(p_lo) = __halves2bfloat162(l0, l1);
}

// ---------------- inv_freq table ----------------
__global__ void init_invfreq_kernel()
{
    int i = threadIdx.x;
    g_invfreq[i] = (float)(1.0 / pow(10000.0, (double)(2 * i) / 64.0));
}

// ---------------- RMSNorm fused with [hi|lo] split ----------------
__global__ __launch_bounds__(256)
void rmsnorm_split_kernel(const float* __restrict__ x, const float* __restrict__ w)
{
    int row = blockIdx.x;
    const float* xr = x + (size_t)row * DIM;
    int tid = threadIdx.x;

    float4 v = ((const float4*)xr)[tid];
    float ss = v.x * v.x + v.y * v.y + v.z * v.z + v.w * v.w;
    #pragma unroll
    for (int o = 16; o > 0; o >>= 1) ss += __shfl_xor_sync(0xffffffffu, ss, o);

    __shared__ float warpsum[8];
    __shared__ float rstd_s;
    if ((tid & 31) == 0) warpsum[tid >> 5] = ss;
    __syncthreads();
    if (tid == 0) {
        float t = 0.f;
        #pragma unroll
        for (int i = 0; i < 8; i++) t += warpsum[i];
        rstd_s = rsqrtf(t * (1.0f / DIM) + 1.1920929e-07f);
    }
    __syncthreads();
    float rstd = rstd_s;

    float4 wv = ((const float4*)w)[tid];
    float4 o4 = make_float4(v.x * rstd * wv.x, v.y * rstd * wv.y,
                            v.z * rstd * wv.z, v.w * rstd * wv.w);
    __nv_bfloat16* base = g_xc + (size_t)row * KC2;
    int col = tid * 4;
    split_store4(base + col, base + 1024 + col, o4);
}

// ---------------- weight [hi|lo] split ----------------
__global__ __launch_bounds__(256)
void convert_w_kernel(const float* __restrict__ w0, const float* __restrict__ w1,
                      const float* __restrict__ w2, const float* __restrict__ w3)
{
    int z = blockIdx.z;
    const float* w = (z == 0) ? w0 : (z == 1) ? w1 : (z == 2) ? w2 : w3;
    int p = blockIdx.x * 256 + threadIdx.x;
    int row = p >> 8;
    int c4 = (p & 255) * 4;
    float4 v = *(const float4*)(w + (size_t)row * 1024 + c4);
    __nv_bfloat16* base = g_wc + (size_t)z * WSZ2 + (size_t)row * KC2;
    split_store4(base + c4, base + 1024 + c4, v);
}

// ---------------- 3-product hi/lo GEMM: C = Ah*Bh^T + Ah*Bl^T + Al*Bh^T -----
// CTA 128x128, 8 warps (2m x 4n), BK=32 over base K=1024, double buffered,
// cp.async global->smem. Smem: per stage 4 sections (Ah,Al,Bh,Bl) 128x40 bf16.
#define ST2   40
#define SSEC  (128 * ST2 * 2)     // 10240 B
#define STAGE (4 * SSEC)          // 40960 B
#define NK2   (1024 / 32)         // 32 steps

__global__ __launch_bounds__(256, 2)
void gemm_mma2_kernel(const __nv_bfloat16* __restrict__ A,
                      const __nv_bfloat16* __restrict__ B0,
                      const __nv_bfloat16* __restrict__ B1,
                      const __nv_bfloat16* __restrict__ B2,
                      float* __restrict__ C0, float* __restrict__ C1,
                      float* __restrict__ C2)
{
    extern __shared__ __align__(16) char smc[];   // 2 * STAGE

    int z = blockIdx.z;
    const __nv_bfloat16* B = (z == 0) ? B0 : (z == 1) ? B1 : B2;
    float* C = (z == 0) ? C0 : (z == 1) ? C1 : C2;

    const int tid = threadIdx.x;
    const int wid = tid >> 5;
    const int lane = tid & 31;
    const int warp_m = wid & 1;
    const int warp_n = wid >> 1;
    const int bm = blockIdx.y * 128;
    const int bn = blockIdx.x * 128;

    const uint32_t smb = smem_to_u32(smc);

    // copy mapping: thread -> (row, 16-elem chunk)
    const int crow = tid >> 1;
    const int ce = (tid & 1) * 16;
    const __nv_bfloat16* Agh = A + (size_t)(bm + crow) * KC2 + ce;
    const __nv_bfloat16* Agl = Agh + 1024;
    const __nv_bfloat16* Bgh = B + (size_t)(bn + crow) * KC2 + ce;
    const __nv_bfloat16* Bgl = Bgh + 1024;
    const uint32_t soff = (uint32_t)(crow * ST2 + ce) * 2;

    // ldmatrix per-lane offsets (within a section)
    const uint32_t a_off = (uint32_t)((warp_m * 64 + (lane & 15)) * ST2
                                      + (lane >> 4) * 8) * 2;
    const int bl = lane & 15;
    const uint32_t b_off = (uint32_t)((warp_n * 32 + (bl & 7)) * ST2
                                      + ((bl >> 3) & 1) * 8) * 2;

    float acc[4][4][4];
    #pragma unroll
    for (int im = 0; im < 4; im++)
        #pragma unroll
        for (int in = 0; in < 4; in++)
            #pragma unroll
            for (int r = 0; r < 4; r++) acc[im][in][r] = 0.f;

    // prologue: stage 0
    {
        uint32_t sb = smb + soff;
        CP16(sb + 0 * SSEC,      Agh); CP16(sb + 0 * SSEC + 16, Agh + 8);
        CP16(sb + 1 * SSEC,      Agl); CP16(sb + 1 * SSEC + 16, Agl + 8);
        CP16(sb + 2 * SSEC,      Bgh); CP16(sb + 2 * SSEC + 16, Bgh + 8);
        CP16(sb + 3 * SSEC,      Bgl); CP16(sb + 3 * SSEC + 16, Bgl + 8);
        CP_COMMIT();
    }

    int buf = 0;
    for (int c = 0; c < NK2; c++) {
        CP_WAIT0();
        __syncthreads();

        if (c + 1 < NK2) {
            int ko = (c + 1) * 32;
            uint32_t sb = smb + (buf ^ 1) * STAGE + soff;
            CP16(sb + 0 * SSEC,      Agh + ko); CP16(sb + 0 * SSEC + 16, Agh + ko + 8);
            CP16(sb + 1 * SSEC,      Agl + ko); CP16(sb + 1 * SSEC + 16, Agl + ko + 8);
            CP16(sb + 2 * SSEC,      Bgh + ko); CP16(sb + 2 * SSEC + 16, Bgh + ko + 8);
            CP16(sb + 3 * SSEC,      Bgl + ko); CP16(sb + 3 * SSEC + 16, Bgl + ko + 8);
            CP_COMMIT();
        }

        const uint32_t sAh = smb + buf * STAGE;
        const uint32_t sAl = sAh + SSEC;
        const uint32_t sBh = sAl + SSEC;
        const uint32_t sBl = sBh + SSEC;

        #pragma unroll
        for (int ik = 0; ik < 2; ik++) {
            uint32_t afh[4][4], afl[4][4];
            #pragma unroll
            for (int im = 0; im < 4; im++) {
                uint32_t ao = a_off + (uint32_t)(im * 16 * ST2) * 2 + ik * 32;
                ldsm_x4(afh[im], sAh + ao);
                ldsm_x4(afl[im], sAl + ao);
            }
            #pragma unroll
            for (int in = 0; in < 4; in++) {
                uint32_t bo = b_off + (uint32_t)(in * 8 * ST2) * 2 + ik * 32;
                uint32_t bh_[2], bl_[2];
                ldsm_x2(bh_, sBh + bo);
                ldsm_x2(bl_, sBl + bo);
                #pragma unroll
                for (int im = 0; im < 4; im++) {
                    mma16816(acc[im][in], afh[im], bh_);
                    mma16816(acc[im][in], afh[im], bl_);
                    mma16816(acc[im][in], afl[im], bh_);
                }
            }
        }
        __syncthreads();
        buf ^= 1;
    }

    const int g = lane >> 2, t = lane & 3;
    #pragma unroll
    for (int im = 0; im < 4; im++) {
        int r0 = bm + warp_m * 64 + im * 16 + g;
        #pragma unroll
        for (int in = 0; in < 4; in++) {
            int c0 = bn + warp_n * 32 + in * 8 + t * 2;
            float2 lo = make_float2(acc[im][in][0], acc[im][in][1]);
            float2 hi = make_float2(acc[im][in][2], acc[im][in][3]);
            *(float2*)(C + (size_t)r0 * GN + c0) = lo;
            *(float2*)(C + (size_t)(r0 + 8) * GN + c0) = hi;
        }
    }
}

// ---------------- RoPE + hi/lo split to bf16 ----------------
__global__ __launch_bounds__(256)
void rope_split_kernel(const float* __restrict__ x, __nv_bfloat16* __restrict__ xh,
                       __nv_bfloat16* __restrict__ xl, float scale)
{
    int p = blockIdx.x * blockDim.x + threadIdx.x;
    int pd  = p & 511;
    int row = p >> 9;
    int tok = row & (NTOK - 1);
    int i   = pd & 31;

    float inv = g_invfreq[i];
    float ang = (float)tok * inv;
    float s, c;
    sincosf(ang, &s, &c);

    const float* px = x + (size_t)row * DIM + 2 * pd;
    float x0 = px[0] * scale, x1 = px[1] * scale;
    float r0 = x0 * c - x1 * s;
    float r1 = x1 * c + x0 * s;

    __nv_bfloat16 h0 = __float2bfloat16(r0), h1 = __float2bfloat16(r1);
    __nv_bfloat16 l0 = __float2bfloat16(r0 - __bfloat162float(h0));
    __nv_bfloat16 l1 = __float2bfloat16(r1 - __bfloat162float(h1));
    size_t off = (size_t)row * DIM + 2 * pd;
    *(__nv_bfloat162*)(xh + off) = __halves2bfloat162(h0, h1);
    *(__nv_bfloat162*)(xl + off) = __halves2bfloat162(l0, l1);
}

// ---------------- V transpose + split: [b,tok,h*64+d] -> [b,h,d,tok] --------
__global__ __launch_bounds__(256)
void v_split_tr_kernel(const float* __restrict__ v)
{
    __shared__ float st[64][65];
    int bh = blockIdx.y, b = bh >> 4, h = bh & 15;
    int t0 = blockIdx.x * 64;
    int tid = threadIdx.x;

    #pragma unroll
    for (int u = 0; u < 16; u++) {
        int idx = tid + u * 256;
        int row = idx >> 6, col = idx & 63;
        st[row][col] = v[(size_t)(b * NTOK + t0 + row) * DIM + h * 64 + col];
    }
    __syncthreads();

    int d = tid >> 2, ch = (tid & 3) * 16;
    size_t obase = ((size_t)bh * 64 + d) * NTOK + t0 + ch;
    #pragma unroll
    for (int i = 0; i < 16; i++) {
        float val = st[ch + i][d];
        __nv_bfloat16 hi = __float2bfloat16(val);
        __nv_bfloat16 lo = __float2bfloat16(val - __bfloat162float(hi));
        g_vth[obase + i] = hi;
        g_vtl[obase + i] = lo;
    }
}

// ---------------- Tensor-core causal flash attention (hi/lo split) ----------
#define AST 72

__global__ __launch_bounds__(128)
void attn_mma_kernel(const __nv_bfloat16* __restrict__ qh, const __nv_bfloat16* __restrict__ ql,
                     const __nv_bfloat16* __restrict__ kh, const __nv_bfloat16* __restrict__ kl)
{
    __shared__ __align__(16) char smraw[4 * 64 * AST * 2];
    const uint32_t smb = smem_to_u32(smraw);

    int tid = threadIdx.x, w = tid >> 5, lane = tid & 31;
    int g = lane >> 2, t = lane & 3, bl = lane & 15;
    int bh = blockIdx.y, b = bh >> 4, h = bh & 15;
    int qbase = blockIdx.x * 64;

    #pragma unroll
    for (int u = 0; u < 8; u++) {
        int cid = tid + u * 128;
        int arr = cid >> 9, rem = cid & 511, row = rem >> 3, ci = rem & 7;
        const __nv_bfloat16* src = (arr ? ql : qh)
            + (size_t)(b * NTOK + qbase + row) * DIM + h * 64 + ci * 8;
        *(uint4*)(smraw + (arr * 64 * AST + row * AST + ci * 8) * 2) = *(const uint4*)src;
    }
    __syncthreads();

    uint32_t qfh[4][4], qfl[4][4];
    {
        uint32_t abase = smb + (uint32_t)((w * 16 + bl) * AST + (lane >> 4) * 8) * 2;
        #pragma unroll
        for (int kk = 0; kk < 4; kk++) {
            ldsm_x4(qfh[kk], abase + kk * 32);
            ldsm_x4(qfl[kk], abase + 64 * AST * 2 + kk * 32);
        }
    }
    __syncthreads();

    float O[8][4];
    #pragma unroll
    for (int nn = 0; nn < 8; nn++)
        #pragma unroll
        for (int r = 0; r < 4; r++) O[nn][r] = 0.f;
    float m0 = -1e30f, m1 = -1e30f, l0 = 0.f, l1 = 0.f;
    const int wmin = qbase + w * 16;
    const int r0g = wmin + g, r1g = r0g + 8;

    for (int j0 = 0; j0 <= qbase; j0 += 64) {
        #pragma unroll
        for (int u = 0; u < 16; u++) {
            int cid = tid + u * 128;
            int tile = cid >> 9, rem = cid & 511, row = rem >> 3, ci = rem & 7;
            const __nv_bfloat16* src;
            if (tile == 0)      src = kh + (size_t)(b * NTOK + j0 + row) * DIM + h * 64 + ci * 8;
            else if (tile == 1) src = kl + (size_t)(b * NTOK + j0 + row) * DIM + h * 64 + ci * 8;
            else if (tile == 2) src = g_vth + ((size_t)bh * 64 + row) * NTOK + j0 + ci * 8;
            else                src = g_vtl + ((size_t)bh * 64 + row) * NTOK + j0 + ci * 8;
            *(uint4*)(smraw + (tile * 64 * AST + row * AST + ci * 8) * 2) = *(const uint4*)src;
        }
        __syncthreads();

        float S[8][4];
        #pragma unroll
        for (int nn = 0; nn < 8; nn++)
            #pragma unroll
            for (int r = 0; r < 4; r++) S[nn][r] = 0.f;

        const uint32_t kboff = smb + (uint32_t)((bl & 7) * AST + ((bl >> 3) & 1) * 8) * 2;
        #pragma unroll
        for (int nn = 0; nn < 8; nn++) {
            #pragma unroll
            for (int kk = 0; kk < 4; kk++) {
                uint32_t kfh[2], kfl[2];
                uint32_t ad = kboff + (uint32_t)(nn * 8 * AST) * 2 + kk * 32;
                ldsm_x2(kfh, ad);
                ldsm_x2(kfl, ad + 64 * AST * 2);
                mma16816(S[nn], qfh[kk], kfh);
                mma16816(S[nn], qfh[kk], kfl);
                mma16816(S[nn], qfl[kk], kfh);
            }
        }

        if (j0 + 63 > wmin) {
            #pragma unroll
            for (int nn = 0; nn < 8; nn++) {
                int jg = j0 + nn * 8 + 2 * t;
                if (jg     > r0g) S[nn][0] = -1e30f;
                if (jg + 1 > r0g) S[nn][1] = -1e30f;
                if (jg     > r1g) S[nn][2] = -1e30f;
                if (jg + 1 > r1g) S[nn][3] = -1e30f;
            }
        }

        float mt0 = -1e30f, mt1 = -1e30f;
        #pragma unroll
        for (int nn = 0; nn < 8; nn++) {
            mt0 = fmaxf(mt0, fmaxf(S[nn][0], S[nn][1]));
            mt1 = fmaxf(mt1, fmaxf(S[nn][2], S[nn][3]));
        }
        mt0 = fmaxf(mt0, __shfl_xor_sync(0xffffffffu, mt0, 1));
        mt0 = fmaxf(mt0, __shfl_xor_sync(0xffffffffu, mt0, 2));
        mt1 = fmaxf(mt1, __shfl_xor_sync(0xffffffffu, mt1, 1));
        mt1 = fmaxf(mt1, __shfl_xor_sync(0xffffffffu, mt1, 2));

        float mnew0 = fmaxf(m0, mt0), mnew1 = fmaxf(m1, mt1);
        float alpha0 = __expf(m0 - mnew0), alpha1 = __expf(m1 - mnew1);
        m0 = mnew0; m1 = mnew1;

        float rs0 = 0.f, rs1 = 0.f;
        uint32_t ah[4][4], al[4][4];
        #pragma unroll
        for (int nn = 0; nn < 8; nn++) {
            float p0 = __expf(S[nn][0] - mnew0);
            float p1 = __expf(S[nn][1] - mnew0);
            float p2 = __expf(S[nn][2] - mnew1);
            float p3 = __expf(S[nn][3] - mnew1);
            rs0 += p0 + p1; rs1 += p2 + p3;
            float h0 = __bfloat162float(__float2bfloat16(p0));
            float h1 = __bfloat162float(__float2bfloat16(p1));
            float h2 = __bfloat162float(__float2bfloat16(p2));
            float h3 = __bfloat162float(__float2bfloat16(p3));
            int kk = nn >> 1, pt = (nn & 1) * 2;
            ah[kk][pt]     = pack_bf2(h0, h1);
            ah[kk][pt + 1] = pack_bf2(h2, h3);
            al[kk][pt]     = pack_bf2(p0 - h0, p1 - h1);
            al[kk][pt + 1] = pack_bf2(p2 - h2, p3 - h3);
        }
        rs0 += __shfl_xor_sync(0xffffffffu, rs0, 1);
        rs0 += __shfl_xor_sync(0xffffffffu, rs0, 2);
        rs1 += __shfl_xor_sync(0xffffffffu, rs1, 1);
        rs1 += __shfl_xor_sync(0xffffffffu, rs1, 2);
        l0 = l0 * alpha0 + rs0;
        l1 = l1 * alpha1 + rs1;

        #pragma unroll
        for (int nn = 0; nn < 8; nn++) {
            O[nn][0] *= alpha0; O[nn][1] *= alpha0;
            O[nn][2] *= alpha1; O[nn][3] *= alpha1;
        }

        const uint32_t vboff = smb + (uint32_t)(2 * 64 * AST) * 2
                             + (uint32_t)((bl & 7) * AST + ((bl >> 3) & 1) * 8) * 2;
        #pragma unroll
        for (int nn = 0; nn < 8; nn++) {
            #pragma unroll
            for (int kk = 0; kk < 4; kk++) {
                uint32_t vfh[2], vfl[2];
                uint32_t ad = vboff + (uint32_t)(nn * 8 * AST) * 2 + kk * 32;
                ldsm_x2(vfh, ad);
                ldsm_x2(vfl, ad + 64 * AST * 2);
                mma16816(O[nn], ah[kk], vfh);
                mma16816(O[nn], ah[kk], vfl);
                mma16816(O[nn], al[kk], vfh);
            }
        }
        __syncthreads();
    }

    float inv0 = 1.f / l0, inv1 = 1.f / l1;
    __nv_bfloat16* ac0 = g_ac + (size_t)(b * NTOK + r0g) * KC2;
    __nv_bfloat16* ac1 = g_ac + (size_t)(b * NTOK + r1g) * KC2;
    #pragma unroll
    for (int nn = 0; nn < 8; nn++) {
        int col = h * 64 + nn * 8 + 2 * t;
        split_store2(ac0 + col, ac0 + 1024 + col, O[nn][0] * inv0, O[nn][1] * inv0);
        split_store2(ac1 + col, ac1 + 1024 + col, O[nn][2] * inv1, O[nn][3] * inv1);
    }
}

// ---------------- launch ----------------
extern "C" void kernel_launch(void* const* d_in, const int* in_sizes, int n_in,
                              void* d_out, int out_size)
{
    const float* tokens = (const float*)d_in[0];
    const float* nw     = (const float*)d_in[1];
    const float* wq     = (const float*)d_in[2];
    const float* wk     = (const float*)d_in[3];
    const float* wv     = (const float*)d_in[4];
    const float* wo     = (const float*)d_in[5];
    float* out = (float*)d_out;

    float *qb, *kb, *vb;
    __nv_bfloat16 *xc, *ac, *wc, *qhp, *qlp, *khp, *klp;
    cudaGetSymbolAddress((void**)&qb, g_q);
    cudaGetSymbolAddress((void**)&kb, g_k);
    cudaGetSymbolAddress((void**)&vb, g_v);
    cudaGetSymbolAddress((void**)&xc, g_xc);
    cudaGetSymbolAddress((void**)&ac, g_ac);
    cudaGetSymbolAddress((void**)&wc, g_wc);
    cudaGetSymbolAddress((void**)&qhp, g_qh);
    cudaGetSymbolAddress((void**)&qlp, g_ql);
    cudaGetSymbolAddress((void**)&khp, g_kh);
    cudaGetSymbolAddress((void**)&klp, g_kl);

    init_invfreq_kernel<<<1, 32>>>();
    convert_w_kernel<<<dim3(1024, 1, 4), 256>>>(wq, wk, wv, wo);
    rmsnorm_split_kernel<<<NROWS, 256>>>(tokens, nw);

    const int GEMM_SMEM = 2 * STAGE;   // 81920
    cudaFuncSetAttribute(gemm_mma2_kernel, cudaFuncAttributeMaxDynamicSharedMemorySize, GEMM_SMEM);

    // QKV: fused launch (768 CTAs)
    gemm_mma2_kernel<<<dim3(8, 32, 3), 256, GEMM_SMEM>>>(
        xc, wc, wc + WSZ2, wc + 2 * WSZ2, qb, kb, vb);

    int pairs = NROWS * DIM / 2;
    rope_split_kernel<<<pairs / 256, 256>>>(qb, qhp, qlp, 0.125f);
    rope_split_kernel<<<pairs / 256, 256>>>(kb, khp, klp, 1.0f);
    v_split_tr_kernel<<<dim3(NTOK / 64, NB * NHEADS), 256>>>(vb);

    // Tensor-core flash attention
    attn_mma_kernel<<<dim3(NTOK / 64, NB * NHEADS), 128>>>(qhp, qlp, khp, klp);

    // Output projection
    gemm_mma2_kernel<<<dim3(8, 32, 1), 256, GEMM_SMEM>>>(
        ac, wc + 3 * WSZ2, wc + 3 * WSZ2, wc + 3 * WSZ2, out, out, out);
}